// round 12
// baseline (speedup 1.0000x reference)
#include <cuda_runtime.h>
#include <math_constants.h>
#include <cstdint>

#define NSAMPLE 16
#define NPTS    8192
#define BATCH   2
#define CH      64
#define OUTCH   128
#define HSEG    2048              // candidates per (pass, half)
#define KBT     256               // knn block threads

typedef unsigned long long ull;
typedef unsigned int uint;
typedef unsigned short ushort;

// ---- f32x2 packed helpers (Blackwell) ----
__device__ __forceinline__ ull pk2(float a, float b) {
    ull r; asm("mov.b64 %0,{%1,%2};" : "=l"(r) : "f"(a), "f"(b)); return r;
}
__device__ __forceinline__ void upk2(float& a, float& b, ull r) {
    asm("mov.b64 {%0,%1}, %2;" : "=f"(a), "=f"(b) : "l"(r));
}
__device__ __forceinline__ ull fma2_(ull a, ull b, ull c) {
    ull d; asm("fma.rn.f32x2 %0,%1,%2,%3;" : "=l"(d) : "l"(a), "l"(b), "l"(c)); return d;
}
__device__ __forceinline__ ull mul2_(ull a, ull b) {
    ull d; asm("mul.rn.f32x2 %0,%1,%2;" : "=l"(d) : "l"(a), "l"(b)); return d;
}
__device__ __forceinline__ float leaky(float x) { return x >= 0.0f ? x : 0.1f * x; }
__device__ __forceinline__ uint umax_(uint a, uint b) { return a > b ? a : b; }

#define WSTR 68

// scratch
__device__ float4 g_pts4[2 * BATCH * NPTS];
__device__ uint   g_skey[2 * BATCH * NPTS * 2 * NSAMPLE];  // checkpoint keys [q][half][k]
__device__ ushort g_sidg[2 * BATCH * NPTS * 2 * NSAMPLE];  // checkpoint idx
__device__ float2 g_part[2 * BATCH * NPTS * 2 * NSAMPLE];  // final per-half (d, idx)
__device__ int    g_knn[2 * BATCH * NPTS * NSAMPLE];
__device__ float  g_ms[2 * BATCH * NPTS * CH];
__device__ __align__(16) float g_w0T[64 * WSTR];
__device__ __align__(16) float g_w1T[64 * WSTR];

// ---------------------------------------------------------------------------
__global__ void pack_kernel(const float* __restrict__ pc1,
                            const float* __restrict__ pc2) {
    int i = blockIdx.x * blockDim.x + threadIdx.x;
    if (i >= 2 * BATCH * NPTS) return;
    const float* src = (i < BATCH * NPTS) ? pc1 : pc2;
    int r = (i < BATCH * NPTS) ? i : (i - BATCH * NPTS);
    float x = src[r * 3 + 0], y = src[r * 3 + 1], z = src[r * 3 + 2];
    g_pts4[i] = make_float4(x, y, z, x * x + y * y + z * z);
}

__global__ void wprep_kernel(const float* __restrict__ w0,
                             const float* __restrict__ w1) {
    int f = blockIdx.x * blockDim.x + threadIdx.x;   // float4 index, 1024 total
    if (f >= 1024) return;
    float4 a = reinterpret_cast<const float4*>(w0)[f];
    float4 c = reinterpret_cast<const float4*>(w1)[f];
    int o = f >> 4, c0 = (f & 15) * 4;
    g_w0T[(c0 + 0) * WSTR + o] = a.x;
    g_w0T[(c0 + 1) * WSTR + o] = a.y;
    g_w0T[(c0 + 2) * WSTR + o] = a.z;
    g_w0T[(c0 + 3) * WSTR + o] = a.w;
    g_w1T[(c0 + 0) * WSTR + o] = c.x;
    g_w1T[(c0 + 1) * WSTR + o] = c.y;
    g_w1T[(c0 + 2) * WSTR + o] = c.z;
    g_w1T[(c0 + 3) * WSTR + o] = c.w;
}

// ---------------------------------------------------------------------------
// KNN: 2 parallel half-states per query (blockIdx.z), each chained over 2
// passes. State h, pass p scans [4096p + 2048h, +2048). Pass 0 checkpoints
// (keys, idx); pass 1 resumes and emits (d, idx) to g_part for the merge.
// Body identical to R8/R11: uint keys (dist bits | slot, dist >= 0),
// slot-major ushort index smem, 8-candidate batches, shifted threshold,
// wd reconstructed with slot bits MASKED.
// ---------------------------------------------------------------------------
__global__ void __launch_bounds__(KBT) knn_part(int pass) {
    extern __shared__ float ks[];
    float*  sx = ks;
    float*  sy = sx + HSEG;
    float*  sz = sy + HSEG;
    float*  sw = sz + HSEG;
    ushort* sidx = (ushort*)(sw + HSEG);     // [16][KBT], holds GLOBAL idx

    const int dirb = blockIdx.y;             // dir*2 + b
    const int dir  = dirb >> 1;
    const int b    = dirb & 1;
    const int half = blockIdx.z;
    const int tid  = threadIdx.x;
    const int n    = blockIdx.x * KBT + tid;
    const int base = pass * 4096 + half * HSEG;
    const size_t q  = (size_t)dirb * NPTS + n;
    const size_t qh = q * 2 + half;

    const float4* Qb = g_pts4 + ((size_t)dir * BATCH + b) * NPTS;
    const float4* Cb = g_pts4 + ((size_t)(1 - dir) * BATCH + b) * NPTS + base;

    uint bk[NSAMPLE];
    uint wdkey;

    if (pass == 0) {
#pragma unroll
        for (int k = 0; k < NSAMPLE; k++) {
            bk[k] = 0x7F800000u | k;
            sidx[k * KBT + tid] = 0;
        }
        wdkey = 0x7F80000Fu;
    } else {
#pragma unroll
        for (int k = 0; k < NSAMPLE; k++) {
            bk[k] = g_skey[qh * NSAMPLE + k];
            sidx[(bk[k] & 15u) * KBT + tid] = g_sidg[qh * NSAMPLE + k];
        }
        uint m0[8];
#pragma unroll
        for (int k = 0; k < 8; k++) m0[k] = umax_(bk[2*k], bk[2*k+1]);
        uint m1[4];
#pragma unroll
        for (int k = 0; k < 4; k++) m1[k] = umax_(m0[2*k], m0[2*k+1]);
        wdkey = umax_(umax_(m1[0], m1[1]), umax_(m1[2], m1[3]));
    }

    for (int i = tid; i < HSEG; i += KBT) {
        float4 c = Cb[i];
        sx[i] = c.x; sy[i] = c.y; sz[i] = c.z; sw[i] = c.w;
    }
    __syncthreads();

    const float4 qv = Qb[n];
    const float sq1 = qv.w;
    const ull qx2 = pk2(qv.x, qv.x);
    const ull qy2 = pk2(qv.y, qv.y);
    const ull qz2 = pk2(qv.z, qv.z);
    const ull m2  = pk2(-2.0f, -2.0f);

    float wds = __uint_as_float(wdkey & 0xFFFFFFF0u) - sq1;

#pragma unroll 1
    for (int j = 0; j < HSEG; j += 8) {
        ulonglong2 X0 = *reinterpret_cast<const ulonglong2*>(&sx[j]);
        ulonglong2 X1 = *reinterpret_cast<const ulonglong2*>(&sx[j + 4]);
        ulonglong2 Y0 = *reinterpret_cast<const ulonglong2*>(&sy[j]);
        ulonglong2 Y1 = *reinterpret_cast<const ulonglong2*>(&sy[j + 4]);
        ulonglong2 Z0 = *reinterpret_cast<const ulonglong2*>(&sz[j]);
        ulonglong2 Z1 = *reinterpret_cast<const ulonglong2*>(&sz[j + 4]);
        ulonglong2 W0 = *reinterpret_cast<const ulonglong2*>(&sw[j]);
        ulonglong2 W1 = *reinterpret_cast<const ulonglong2*>(&sw[j + 4]);

        ull t0 = fma2_(qx2, X0.x, fma2_(qy2, Y0.x, mul2_(qz2, Z0.x)));
        ull t1 = fma2_(qx2, X0.y, fma2_(qy2, Y0.y, mul2_(qz2, Z0.y)));
        ull t2 = fma2_(qx2, X1.x, fma2_(qy2, Y1.x, mul2_(qz2, Z1.x)));
        ull t3 = fma2_(qx2, X1.y, fma2_(qy2, Y1.y, mul2_(qz2, Z1.y)));
        ull s01 = fma2_(m2, t0, W0.x);
        ull s23 = fma2_(m2, t1, W0.y);
        ull s45 = fma2_(m2, t2, W1.x);
        ull s67 = fma2_(m2, t3, W1.y);

        float s[8];
        upk2(s[0], s[1], s01);
        upk2(s[2], s[3], s23);
        upk2(s[4], s[5], s45);
        upk2(s[6], s[7], s67);

        float m4a = fminf(fminf(s[0], s[1]), fminf(s[2], s[3]));
        float m4b = fminf(fminf(s[4], s[5]), fminf(s[6], s[7]));
        float m8  = fminf(m4a, m4b);

        if (m8 < wds) {
#pragma unroll
            for (int g = 0; g < 2; g++) {
                float mg = g ? m4b : m4a;
                if (mg < wds) {
#pragma unroll
                    for (int t = 0; t < 4; t++) {
                        float sv = s[g * 4 + t];
                        if (sv < wds) {
                            float d = sv + sq1;
                            uint slot = wdkey & 15u;
                            uint nk = (__float_as_uint(fmaxf(d, 0.0f)) & 0xFFFFFFF0u) | slot;
                            sidx[slot * KBT + tid] = (ushort)(base + j + g * 4 + t);
#pragma unroll
                            for (int k = 0; k < NSAMPLE; k++)
                                bk[k] = (bk[k] == wdkey) ? nk : bk[k];
                            uint m0[8];
#pragma unroll
                            for (int k = 0; k < 8; k++) m0[k] = umax_(bk[2*k], bk[2*k+1]);
                            uint m1[4];
#pragma unroll
                            for (int k = 0; k < 4; k++) m1[k] = umax_(m0[2*k], m0[2*k+1]);
                            wdkey = umax_(umax_(m1[0], m1[1]), umax_(m1[2], m1[3]));
                            wds = __uint_as_float(wdkey & 0xFFFFFFF0u) - sq1;
                        }
                    }
                }
            }
        }
    }

    if (pass == 0) {
#pragma unroll
        for (int k = 0; k < NSAMPLE; k++) {
            g_skey[qh * NSAMPLE + k] = bk[k];
            g_sidg[qh * NSAMPLE + k] = sidx[(bk[k] & 15u) * KBT + tid];
        }
    } else {
        float2* outp = g_part + qh * NSAMPLE;
#pragma unroll
        for (int k = 0; k < NSAMPLE; k++) {
            int idx = (int)sidx[(bk[k] & 15u) * KBT + tid];
            outp[k] = make_float2(__uint_as_float(bk[k] & 0xFFFFFFF0u),
                                  __int_as_float(idx));
        }
    }
}

// ---------------------------------------------------------------------------
// Merge: warp per query, 2x16 entries (one per lane) -> exact top-16
// (lex (d, idx) tie-break).
// ---------------------------------------------------------------------------
__global__ void __launch_bounds__(256) knn_merge() {
    const int gtid = blockIdx.x * 256 + threadIdx.x;
    const int q    = gtid >> 5;
    const int lane = gtid & 31;

    float2 e = g_part[(size_t)q * (2 * NSAMPLE) + lane];
    float d = e.x; int i = __float_as_int(e.y);

    int* outp = g_knn + (size_t)q * NSAMPLE;

#pragma unroll
    for (int k = 0; k < NSAMPLE; k++) {
        float bdv = d;
        int   biv = i;
#pragma unroll
        for (int off = 16; off > 0; off >>= 1) {
            float od = __shfl_xor_sync(0xFFFFFFFFu, bdv, off);
            int   oi = __shfl_xor_sync(0xFFFFFFFFu, biv, off);
            if (od < bdv || (od == bdv && oi < biv)) { bdv = od; biv = oi; }
        }
        if (lane == 0) outp[k] = biv;
        if (d == bdv && i == biv) d = CUDART_INF_F;
    }
}

// ---------------------------------------------------------------------------
// feat (unchanged): 128 threads = 8 points x 16 threads; k8 x o8 f32x2
// tiles; weights from pre-transposed global (L1); pm aliases hs.
// ---------------------------------------------------------------------------
#define HROWS 68
#define HPNT  1128

__device__ __forceinline__ int hoff(int p, int k) {
    return p * HPNT + k * HROWS + ((k >> 3) << 4);
}

__global__ void __launch_bounds__(128, 4) feat_kernel(
        const float* __restrict__ feat1,
        const float* __restrict__ feat2,
        const float* __restrict__ pos_w,
        const float* __restrict__ pos_b,
        const float* __restrict__ b0,
        const float* __restrict__ b1) {
    extern __shared__ float sm[];
    float* hs    = sm;                         // 9024
    float* pm    = hs;                         // ALIAS: hs dead after layer 2
    float* posws = hs + 8 * HPNT;              // 192
    float* posbs = posws + 192;                // 64
    float* b0s   = posbs + 64;                 // 64
    float* b1s   = b0s + 64;                   // 64

    const int dir = blockIdx.z;
    const int b   = blockIdx.y;
    const int tid = threadIdx.x;
    const int dirb = dir * BATCH + b;

    if (tid < 64) {
        posbs[tid] = pos_b[tid];
        b0s[tid]   = b0[tid];
        b1s[tid]   = b1[tid];
    }
    for (int i = tid; i < 192; i += 128) posws[i] = pos_w[i];
    __syncthreads();

    const float* F1 = dir ? feat2 : feat1;
    const float* F2 = dir ? feat1 : feat2;
    const float4* QC = g_pts4 + ((size_t)dir * BATCH + b) * NPTS;
    const float4* NC = g_pts4 + ((size_t)(1 - dir) * BATCH + b) * NPTS;

    // ---- stage 1: gather + pos feat + leaky -> hs ----
    {
        const int c  = tid & 63;
        const int rh = tid >> 6;
        const float pwx = posws[c * 3 + 0];
        const float pwy = posws[c * 3 + 1];
        const float pwz = posws[c * 3 + 2];
        const float pb  = posbs[c];
        for (int it = 0; it < 64; it++) {
            int row = it * 2 + rh;
            int p = row >> 4, k = row & 15;
            int n = blockIdx.x * 8 + p;
            int id = g_knn[((size_t)dirb * NPTS + n) * NSAMPLE + k];
            float4 cc = NC[id];
            float4 qq = QC[n];
            float g   = F2[((size_t)b * NPTS + id) * CH + c];
            float p1o = F1[((size_t)b * NPTS + n) * CH + c];
            float h = g + p1o +
                fmaf(pwx, cc.x - qq.x, fmaf(pwy, cc.y - qq.y,
                fmaf(pwz, cc.z - qq.z, pb)));
            hs[hoff(p, k) + c] = leaky(h);
        }
    }
    __syncthreads();

    const int tt = tid & 15;
    const int p  = tid >> 4;
    const int o0 = (tt & 7) * 8;
    const int k0 = (tt >> 3) * 8;
    float* hp2 = hs + hoff(p, k0);

    ull acc[8][4];

    // =============== layer 1 ===============
    {
        ulonglong2 bA = *reinterpret_cast<const ulonglong2*>(b0s + o0);
        ulonglong2 bB = *reinterpret_cast<const ulonglong2*>(b0s + o0 + 4);
#pragma unroll
        for (int ki = 0; ki < 8; ki++) {
            acc[ki][0] = bA.x; acc[ki][1] = bA.y;
            acc[ki][2] = bB.x; acc[ki][3] = bB.y;
        }
#pragma unroll 1
        for (int c = 0; c < 64; c += 4) {
            const float* wp = g_w0T + c * WSTR + o0;
            ulonglong2 wa0 = *reinterpret_cast<const ulonglong2*>(wp);
            ulonglong2 wa1 = *reinterpret_cast<const ulonglong2*>(wp + 4);
            ulonglong2 wb0 = *reinterpret_cast<const ulonglong2*>(wp + WSTR);
            ulonglong2 wb1 = *reinterpret_cast<const ulonglong2*>(wp + WSTR + 4);
            ulonglong2 wc0 = *reinterpret_cast<const ulonglong2*>(wp + 2 * WSTR);
            ulonglong2 wc1 = *reinterpret_cast<const ulonglong2*>(wp + 2 * WSTR + 4);
            ulonglong2 wd0 = *reinterpret_cast<const ulonglong2*>(wp + 3 * WSTR);
            ulonglong2 wd1 = *reinterpret_cast<const ulonglong2*>(wp + 3 * WSTR + 4);
#pragma unroll
            for (int ki = 0; ki < 8; ki++) {
                float4 hv = *reinterpret_cast<const float4*>(hp2 + ki * HROWS + c);
                ull h0 = pk2(hv.x, hv.x);
                ull h1 = pk2(hv.y, hv.y);
                ull h2 = pk2(hv.z, hv.z);
                ull h3 = pk2(hv.w, hv.w);
                acc[ki][0] = fma2_(h0, wa0.x, acc[ki][0]);
                acc[ki][1] = fma2_(h0, wa0.y, acc[ki][1]);
                acc[ki][2] = fma2_(h0, wa1.x, acc[ki][2]);
                acc[ki][3] = fma2_(h0, wa1.y, acc[ki][3]);
                acc[ki][0] = fma2_(h1, wb0.x, acc[ki][0]);
                acc[ki][1] = fma2_(h1, wb0.y, acc[ki][1]);
                acc[ki][2] = fma2_(h1, wb1.x, acc[ki][2]);
                acc[ki][3] = fma2_(h1, wb1.y, acc[ki][3]);
                acc[ki][0] = fma2_(h2, wc0.x, acc[ki][0]);
                acc[ki][1] = fma2_(h2, wc0.y, acc[ki][1]);
                acc[ki][2] = fma2_(h2, wc1.x, acc[ki][2]);
                acc[ki][3] = fma2_(h2, wc1.y, acc[ki][3]);
                acc[ki][0] = fma2_(h3, wd0.x, acc[ki][0]);
                acc[ki][1] = fma2_(h3, wd0.y, acc[ki][1]);
                acc[ki][2] = fma2_(h3, wd1.x, acc[ki][2]);
                acc[ki][3] = fma2_(h3, wd1.y, acc[ki][3]);
            }
        }
    }
    __syncthreads();
#pragma unroll
    for (int ki = 0; ki < 8; ki++) {
        float a0, a1, a2, a3, a4, a5, a6, a7;
        upk2(a0, a1, acc[ki][0]);
        upk2(a2, a3, acc[ki][1]);
        upk2(a4, a5, acc[ki][2]);
        upk2(a6, a7, acc[ki][3]);
        float4 v0 = make_float4(leaky(a0), leaky(a1), leaky(a2), leaky(a3));
        float4 v1 = make_float4(leaky(a4), leaky(a5), leaky(a6), leaky(a7));
        *reinterpret_cast<float4*>(hp2 + ki * HROWS + o0)     = v0;
        *reinterpret_cast<float4*>(hp2 + ki * HROWS + o0 + 4) = v1;
    }
    __syncthreads();

    // =============== layer 2 ===============
    {
        ulonglong2 bA = *reinterpret_cast<const ulonglong2*>(b1s + o0);
        ulonglong2 bB = *reinterpret_cast<const ulonglong2*>(b1s + o0 + 4);
#pragma unroll
        for (int ki = 0; ki < 8; ki++) {
            acc[ki][0] = bA.x; acc[ki][1] = bA.y;
            acc[ki][2] = bB.x; acc[ki][3] = bB.y;
        }
#pragma unroll 1
        for (int c = 0; c < 64; c += 4) {
            const float* wp = g_w1T + c * WSTR + o0;
            ulonglong2 wa0 = *reinterpret_cast<const ulonglong2*>(wp);
            ulonglong2 wa1 = *reinterpret_cast<const ulonglong2*>(wp + 4);
            ulonglong2 wb0 = *reinterpret_cast<const ulonglong2*>(wp + WSTR);
            ulonglong2 wb1 = *reinterpret_cast<const ulonglong2*>(wp + WSTR + 4);
            ulonglong2 wc0 = *reinterpret_cast<const ulonglong2*>(wp + 2 * WSTR);
            ulonglong2 wc1 = *reinterpret_cast<const ulonglong2*>(wp + 2 * WSTR + 4);
            ulonglong2 wd0 = *reinterpret_cast<const ulonglong2*>(wp + 3 * WSTR);
            ulonglong2 wd1 = *reinterpret_cast<const ulonglong2*>(wp + 3 * WSTR + 4);
#pragma unroll
            for (int ki = 0; ki < 8; ki++) {
                float4 hv = *reinterpret_cast<const float4*>(hp2 + ki * HROWS + c);
                ull h0 = pk2(hv.x, hv.x);
                ull h1 = pk2(hv.y, hv.y);
                ull h2 = pk2(hv.z, hv.z);
                ull h3 = pk2(hv.w, hv.w);
                acc[ki][0] = fma2_(h0, wa0.x, acc[ki][0]);
                acc[ki][1] = fma2_(h0, wa0.y, acc[ki][1]);
                acc[ki][2] = fma2_(h0, wa1.x, acc[ki][2]);
                acc[ki][3] = fma2_(h0, wa1.y, acc[ki][3]);
                acc[ki][0] = fma2_(h1, wb0.x, acc[ki][0]);
                acc[ki][1] = fma2_(h1, wb0.y, acc[ki][1]);
                acc[ki][2] = fma2_(h1, wb1.x, acc[ki][2]);
                acc[ki][3] = fma2_(h1, wb1.y, acc[ki][3]);
                acc[ki][0] = fma2_(h2, wc0.x, acc[ki][0]);
                acc[ki][1] = fma2_(h2, wc0.y, acc[ki][1]);
                acc[ki][2] = fma2_(h2, wc1.x, acc[ki][2]);
                acc[ki][3] = fma2_(h2, wc1.y, acc[ki][3]);
                acc[ki][0] = fma2_(h3, wd0.x, acc[ki][0]);
                acc[ki][1] = fma2_(h3, wd0.y, acc[ki][1]);
                acc[ki][2] = fma2_(h3, wd1.x, acc[ki][2]);
                acc[ki][3] = fma2_(h3, wd1.y, acc[ki][3]);
            }
        }
    }

    __syncthreads();   // hs dead; pm aliases it

    {
        float mx[8];
#pragma unroll
        for (int j = 0; j < 8; j++) mx[j] = -CUDART_INF_F;
#pragma unroll
        for (int ki = 0; ki < 8; ki++) {
            float a0, a1, a2, a3, a4, a5, a6, a7;
            upk2(a0, a1, acc[ki][0]);
            upk2(a2, a3, acc[ki][1]);
            upk2(a4, a5, acc[ki][2]);
            upk2(a6, a7, acc[ki][3]);
            mx[0] = fmaxf(mx[0], leaky(a0));
            mx[1] = fmaxf(mx[1], leaky(a1));
            mx[2] = fmaxf(mx[2], leaky(a2));
            mx[3] = fmaxf(mx[3], leaky(a3));
            mx[4] = fmaxf(mx[4], leaky(a4));
            mx[5] = fmaxf(mx[5], leaky(a5));
            mx[6] = fmaxf(mx[6], leaky(a6));
            mx[7] = fmaxf(mx[7], leaky(a7));
        }
        float* pmp = pm + p * 128 + (k0 >> 3) * 64 + o0;
        *reinterpret_cast<float4*>(pmp)     = make_float4(mx[0], mx[1], mx[2], mx[3]);
        *reinterpret_cast<float4*>(pmp + 4) = make_float4(mx[4], mx[5], mx[6], mx[7]);
    }
    __syncthreads();

#pragma unroll
    for (int i = 0; i < 4; i++) {
        int ii = tid + i * 128;
        int pp = ii >> 6, oo = ii & 63;
        float mm = fmaxf(pm[pp * 128 + oo], pm[pp * 128 + 64 + oo]);
        int nn = blockIdx.x * 8 + pp;
        g_ms[((size_t)dirb * NPTS + nn) * CH + oo] = mm;
    }
}

// ---------------------------------------------------------------------------
// proj (unchanged)
// ---------------------------------------------------------------------------
#define PPROJ 64
__global__ void __launch_bounds__(128) proj_kernel(
        const float* __restrict__ t1w, const float* __restrict__ t1b,
        const float* __restrict__ t2w, const float* __restrict__ t2b,
        float* __restrict__ out) {
    __shared__ float aS[PPROJ * 64];

    const int dir = blockIdx.z;
    const int b   = blockIdx.y;
    const int j   = threadIdx.x;
    const int dirb = dir * BATCH + b;

    const float* tw = dir ? t2w : t1w;
    const float* tb = dir ? t2b : t1b;

    float4 w[16];
#pragma unroll
    for (int t = 0; t < 16; t++)
        w[t] = reinterpret_cast<const float4*>(tw + j * 64)[t];
    const float bias = tb[j];

    const int n0 = blockIdx.x * PPROJ;
#pragma unroll
    for (int i = 0; i < PPROJ * 64 / 128 / 4; i++) {
        int f = j + i * 128;
        reinterpret_cast<float4*>(aS)[f] =
            reinterpret_cast<const float4*>(g_ms + ((size_t)dirb * NPTS + n0) * CH)[f];
    }
    __syncthreads();

#pragma unroll 2
    for (int p = 0; p < PPROJ; p++) {
        float acc = bias;
        const float4* ap = reinterpret_cast<const float4*>(aS + p * 64);
#pragma unroll
        for (int t = 0; t < 16; t++) {
            float4 a = ap[t];
            acc = fmaf(a.x, w[t].x, acc);
            acc = fmaf(a.y, w[t].y, acc);
            acc = fmaf(a.z, w[t].z, acc);
            acc = fmaf(a.w, w[t].w, acc);
        }
        out[((size_t)dirb * NPTS + n0 + p) * OUTCH + j] = acc;
    }
}

// ---------------------------------------------------------------------------
extern "C" void kernel_launch(void* const* d_in, const int* in_sizes, int n_in,
                              void* d_out, int out_size) {
    (void)in_sizes; (void)n_in; (void)out_size;
    const float* pc1   = (const float*)d_in[0];
    const float* pc2   = (const float*)d_in[1];
    const float* feat1 = (const float*)d_in[2];
    const float* feat2 = (const float*)d_in[3];
    const float* pos_w = (const float*)d_in[4];
    const float* pos_b = (const float*)d_in[5];
    const float* w0    = (const float*)d_in[6];
    const float* b0    = (const float*)d_in[7];
    const float* w1    = (const float*)d_in[8];
    const float* b1    = (const float*)d_in[9];
    const float* t1w   = (const float*)d_in[10];
    const float* t1b   = (const float*)d_in[11];
    const float* t2w   = (const float*)d_in[12];
    const float* t2b   = (const float*)d_in[13];
    float* out = (float*)d_out;

    pack_kernel<<<(2 * BATCH * NPTS + 255) / 256, 256>>>(pc1, pc2);
    wprep_kernel<<<4, 256>>>(w0, w1);

    // 32KB candidate tile + 8KB ushort slot-major idx = 40KB
    const size_t ksmem = 4 * HSEG * sizeof(float) + NSAMPLE * KBT * sizeof(ushort);
    cudaFuncSetAttribute(knn_part,
                         cudaFuncAttributeMaxDynamicSharedMemorySize, (int)ksmem);
    dim3 gk(NPTS / KBT, 2 * BATCH, 2);           // x: queries, y: dirb, z: half
    knn_part<<<gk, KBT, ksmem>>>(0);             // halves A,B over first 4096
    knn_part<<<gk, KBT, ksmem>>>(1);             // resume over second 4096

    knn_merge<<<(2 * BATCH * NPTS * 32) / 256, 256>>>();

    const size_t smem = (size_t)(8 * HPNT + 192 + 64 * 3) * sizeof(float);
    cudaFuncSetAttribute(feat_kernel,
                         cudaFuncAttributeMaxDynamicSharedMemorySize, (int)smem);
    dim3 gf(NPTS / 8, BATCH, 2);
    feat_kernel<<<gf, 128, smem>>>(feat1, feat2, pos_w, pos_b, b0, b1);

    dim3 gp(NPTS / PPROJ, BATCH, 2);
    proj_kernel<<<gp, 128>>>(t1w, t1b, t2w, t2b, out);
}

// round 13
// speedup vs baseline: 1.1125x; 1.1125x over previous
#include <cuda_runtime.h>
#include <math_constants.h>
#include <cstdint>

#define NSAMPLE 16
#define NPTS    8192
#define BATCH   2
#define CH      64
#define OUTCH   128
#define SEGSZ   4096              // candidates per tile (2 tiles per kernel)
#define KBT     256               // knn block threads

typedef unsigned long long ull;
typedef unsigned int uint;
typedef unsigned short ushort;

// ---- f32x2 packed helpers (Blackwell) ----
__device__ __forceinline__ ull pk2(float a, float b) {
    ull r; asm("mov.b64 %0,{%1,%2};" : "=l"(r) : "f"(a), "f"(b)); return r;
}
__device__ __forceinline__ void upk2(float& a, float& b, ull r) {
    asm("mov.b64 {%0,%1}, %2;" : "=f"(a), "=f"(b) : "l"(r));
}
__device__ __forceinline__ ull fma2_(ull a, ull b, ull c) {
    ull d; asm("fma.rn.f32x2 %0,%1,%2,%3;" : "=l"(d) : "l"(a), "l"(b), "l"(c)); return d;
}
__device__ __forceinline__ ull mul2_(ull a, ull b) {
    ull d; asm("mul.rn.f32x2 %0,%1,%2;" : "=l"(d) : "l"(a), "l"(b)); return d;
}
__device__ __forceinline__ float leaky(float x) { return x >= 0.0f ? x : 0.1f * x; }
__device__ __forceinline__ uint umax_(uint a, uint b) { return a > b ? a : b; }

#define WSTR 68

// scratch
__device__ float4 g_pts4[2 * BATCH * NPTS];
__device__ int    g_knn[2 * BATCH * NPTS * NSAMPLE];
__device__ float  g_ms[2 * BATCH * NPTS * CH];
__device__ __align__(16) float g_w0T[64 * WSTR];
__device__ __align__(16) float g_w1T[64 * WSTR];

// ---------------------------------------------------------------------------
__global__ void pack_kernel(const float* __restrict__ pc1,
                            const float* __restrict__ pc2) {
    int i = blockIdx.x * blockDim.x + threadIdx.x;
    if (i >= 2 * BATCH * NPTS) return;
    const float* src = (i < BATCH * NPTS) ? pc1 : pc2;
    int r = (i < BATCH * NPTS) ? i : (i - BATCH * NPTS);
    float x = src[r * 3 + 0], y = src[r * 3 + 1], z = src[r * 3 + 2];
    g_pts4[i] = make_float4(x, y, z, x * x + y * y + z * z);
}

__global__ void wprep_kernel(const float* __restrict__ w0,
                             const float* __restrict__ w1) {
    int f = blockIdx.x * blockDim.x + threadIdx.x;   // float4 index, 1024 total
    if (f >= 1024) return;
    float4 a = reinterpret_cast<const float4*>(w0)[f];
    float4 c = reinterpret_cast<const float4*>(w1)[f];
    int o = f >> 4, c0 = (f & 15) * 4;
    g_w0T[(c0 + 0) * WSTR + o] = a.x;
    g_w0T[(c0 + 1) * WSTR + o] = a.y;
    g_w0T[(c0 + 2) * WSTR + o] = a.z;
    g_w0T[(c0 + 3) * WSTR + o] = a.w;
    g_w1T[(c0 + 0) * WSTR + o] = c.x;
    g_w1T[(c0 + 1) * WSTR + o] = c.y;
    g_w1T[(c0 + 2) * WSTR + o] = c.z;
    g_w1T[(c0 + 3) * WSTR + o] = c.w;
}

// ---------------------------------------------------------------------------
// KNN, fused two-tile chained scan. The 4096-candidate smem tile is loaded
// twice inside ONE kernel; the register-resident top-16 carries across tiles
// (warm-up paid once, no checkpoint traffic, no merge).
// Body identical to R8/R11: uint keys (dist bits | slot, dist >= 0),
// slot-major ushort index smem, 8-candidate batches, shifted threshold,
// wd reconstructed with slot bits MASKED (NaN otherwise).
// ---------------------------------------------------------------------------
__global__ void __launch_bounds__(KBT, 3) knn_kernel() {
    extern __shared__ float ks[];
    float*  sx = ks;
    float*  sy = sx + SEGSZ;
    float*  sz = sy + SEGSZ;
    float*  sw = sz + SEGSZ;
    ushort* sidx = (ushort*)(sw + SEGSZ);    // [16][KBT], holds GLOBAL idx

    const int dirb = blockIdx.y;             // dir*2 + b
    const int dir  = dirb >> 1;
    const int b    = dirb & 1;
    const int tid  = threadIdx.x;
    const int n    = blockIdx.x * KBT + tid;
    const size_t q = (size_t)dirb * NPTS + n;

    const float4* Qb = g_pts4 + ((size_t)dir * BATCH + b) * NPTS;
    const float4* Cb0 = g_pts4 + ((size_t)(1 - dir) * BATCH + b) * NPTS;

    uint bk[NSAMPLE];
#pragma unroll
    for (int k = 0; k < NSAMPLE; k++) {
        bk[k] = 0x7F800000u | k;
        sidx[k * KBT + tid] = 0;
    }
    uint wdkey = 0x7F80000Fu;

    const float4 qv = Qb[n];
    const float sq1 = qv.w;
    const ull qx2 = pk2(qv.x, qv.x);
    const ull qy2 = pk2(qv.y, qv.y);
    const ull qz2 = pk2(qv.z, qv.z);
    const ull m2  = pk2(-2.0f, -2.0f);

    float wds = CUDART_INF_F;

#pragma unroll 1
    for (int pass = 0; pass < 2; pass++) {
        const int base = pass * SEGSZ;
        const float4* Cb = Cb0 + base;

        __syncthreads();   // previous sweep done before tile overwrite
        for (int i = tid; i < SEGSZ; i += KBT) {
            float4 c = Cb[i];
            sx[i] = c.x; sy[i] = c.y; sz[i] = c.z; sw[i] = c.w;
        }
        __syncthreads();

#pragma unroll 1
        for (int j = 0; j < SEGSZ; j += 8) {
            ulonglong2 X0 = *reinterpret_cast<const ulonglong2*>(&sx[j]);
            ulonglong2 X1 = *reinterpret_cast<const ulonglong2*>(&sx[j + 4]);
            ulonglong2 Y0 = *reinterpret_cast<const ulonglong2*>(&sy[j]);
            ulonglong2 Y1 = *reinterpret_cast<const ulonglong2*>(&sy[j + 4]);
            ulonglong2 Z0 = *reinterpret_cast<const ulonglong2*>(&sz[j]);
            ulonglong2 Z1 = *reinterpret_cast<const ulonglong2*>(&sz[j + 4]);
            ulonglong2 W0 = *reinterpret_cast<const ulonglong2*>(&sw[j]);
            ulonglong2 W1 = *reinterpret_cast<const ulonglong2*>(&sw[j + 4]);

            ull t0 = fma2_(qx2, X0.x, fma2_(qy2, Y0.x, mul2_(qz2, Z0.x)));
            ull t1 = fma2_(qx2, X0.y, fma2_(qy2, Y0.y, mul2_(qz2, Z0.y)));
            ull t2 = fma2_(qx2, X1.x, fma2_(qy2, Y1.x, mul2_(qz2, Z1.x)));
            ull t3 = fma2_(qx2, X1.y, fma2_(qy2, Y1.y, mul2_(qz2, Z1.y)));
            ull s01 = fma2_(m2, t0, W0.x);
            ull s23 = fma2_(m2, t1, W0.y);
            ull s45 = fma2_(m2, t2, W1.x);
            ull s67 = fma2_(m2, t3, W1.y);

            float s[8];
            upk2(s[0], s[1], s01);
            upk2(s[2], s[3], s23);
            upk2(s[4], s[5], s45);
            upk2(s[6], s[7], s67);

            float m4a = fminf(fminf(s[0], s[1]), fminf(s[2], s[3]));
            float m4b = fminf(fminf(s[4], s[5]), fminf(s[6], s[7]));
            float m8  = fminf(m4a, m4b);

            if (m8 < wds) {
#pragma unroll
                for (int g = 0; g < 2; g++) {
                    float mg = g ? m4b : m4a;
                    if (mg < wds) {
#pragma unroll
                        for (int t = 0; t < 4; t++) {
                            float sv = s[g * 4 + t];
                            if (sv < wds) {
                                float d = sv + sq1;
                                uint slot = wdkey & 15u;
                                uint nk = (__float_as_uint(fmaxf(d, 0.0f)) & 0xFFFFFFF0u) | slot;
                                sidx[slot * KBT + tid] = (ushort)(base + j + g * 4 + t);
#pragma unroll
                                for (int k = 0; k < NSAMPLE; k++)
                                    bk[k] = (bk[k] == wdkey) ? nk : bk[k];
                                uint m0[8];
#pragma unroll
                                for (int k = 0; k < 8; k++) m0[k] = umax_(bk[2*k], bk[2*k+1]);
                                uint m1[4];
#pragma unroll
                                for (int k = 0; k < 4; k++) m1[k] = umax_(m0[2*k], m0[2*k+1]);
                                wdkey = umax_(umax_(m1[0], m1[1]), umax_(m1[2], m1[3]));
                                wds = __uint_as_float(wdkey & 0xFFFFFFF0u) - sq1;
                            }
                        }
                    }
                }
            }
        }
    }

    int* outp = g_knn + q * NSAMPLE;
#pragma unroll
    for (int k = 0; k < NSAMPLE; k++)
        outp[k] = (int)sidx[(bk[k] & 15u) * KBT + tid];
}

// ---------------------------------------------------------------------------
// feat (unchanged R11): 128 threads = 8 points x 16 threads; k8 x o8 f32x2
// tiles; weights from pre-transposed global (L1); pm aliases hs.
// ---------------------------------------------------------------------------
#define HROWS 68
#define HPNT  1128

__device__ __forceinline__ int hoff(int p, int k) {
    return p * HPNT + k * HROWS + ((k >> 3) << 4);
}

__global__ void __launch_bounds__(128, 4) feat_kernel(
        const float* __restrict__ feat1,
        const float* __restrict__ feat2,
        const float* __restrict__ pos_w,
        const float* __restrict__ pos_b,
        const float* __restrict__ b0,
        const float* __restrict__ b1) {
    extern __shared__ float sm[];
    float* hs    = sm;                         // 9024
    float* pm    = hs;                         // ALIAS: hs dead after layer 2
    float* posws = hs + 8 * HPNT;              // 192
    float* posbs = posws + 192;                // 64
    float* b0s   = posbs + 64;                 // 64
    float* b1s   = b0s + 64;                   // 64

    const int dir = blockIdx.z;
    const int b   = blockIdx.y;
    const int tid = threadIdx.x;
    const int dirb = dir * BATCH + b;

    if (tid < 64) {
        posbs[tid] = pos_b[tid];
        b0s[tid]   = b0[tid];
        b1s[tid]   = b1[tid];
    }
    for (int i = tid; i < 192; i += 128) posws[i] = pos_w[i];
    __syncthreads();

    const float* F1 = dir ? feat2 : feat1;
    const float* F2 = dir ? feat1 : feat2;
    const float4* QC = g_pts4 + ((size_t)dir * BATCH + b) * NPTS;
    const float4* NC = g_pts4 + ((size_t)(1 - dir) * BATCH + b) * NPTS;

    // ---- stage 1: gather + pos feat + leaky -> hs ----
    {
        const int c  = tid & 63;
        const int rh = tid >> 6;
        const float pwx = posws[c * 3 + 0];
        const float pwy = posws[c * 3 + 1];
        const float pwz = posws[c * 3 + 2];
        const float pb  = posbs[c];
        for (int it = 0; it < 64; it++) {
            int row = it * 2 + rh;
            int p = row >> 4, k = row & 15;
            int n = blockIdx.x * 8 + p;
            int id = g_knn[((size_t)dirb * NPTS + n) * NSAMPLE + k];
            float4 cc = NC[id];
            float4 qq = QC[n];
            float g   = F2[((size_t)b * NPTS + id) * CH + c];
            float p1o = F1[((size_t)b * NPTS + n) * CH + c];
            float h = g + p1o +
                fmaf(pwx, cc.x - qq.x, fmaf(pwy, cc.y - qq.y,
                fmaf(pwz, cc.z - qq.z, pb)));
            hs[hoff(p, k) + c] = leaky(h);
        }
    }
    __syncthreads();

    const int tt = tid & 15;
    const int p  = tid >> 4;
    const int o0 = (tt & 7) * 8;
    const int k0 = (tt >> 3) * 8;
    float* hp2 = hs + hoff(p, k0);

    ull acc[8][4];

    // =============== layer 1 ===============
    {
        ulonglong2 bA = *reinterpret_cast<const ulonglong2*>(b0s + o0);
        ulonglong2 bB = *reinterpret_cast<const ulonglong2*>(b0s + o0 + 4);
#pragma unroll
        for (int ki = 0; ki < 8; ki++) {
            acc[ki][0] = bA.x; acc[ki][1] = bA.y;
            acc[ki][2] = bB.x; acc[ki][3] = bB.y;
        }
#pragma unroll 1
        for (int c = 0; c < 64; c += 4) {
            const float* wp = g_w0T + c * WSTR + o0;
            ulonglong2 wa0 = *reinterpret_cast<const ulonglong2*>(wp);
            ulonglong2 wa1 = *reinterpret_cast<const ulonglong2*>(wp + 4);
            ulonglong2 wb0 = *reinterpret_cast<const ulonglong2*>(wp + WSTR);
            ulonglong2 wb1 = *reinterpret_cast<const ulonglong2*>(wp + WSTR + 4);
            ulonglong2 wc0 = *reinterpret_cast<const ulonglong2*>(wp + 2 * WSTR);
            ulonglong2 wc1 = *reinterpret_cast<const ulonglong2*>(wp + 2 * WSTR + 4);
            ulonglong2 wd0 = *reinterpret_cast<const ulonglong2*>(wp + 3 * WSTR);
            ulonglong2 wd1 = *reinterpret_cast<const ulonglong2*>(wp + 3 * WSTR + 4);
#pragma unroll
            for (int ki = 0; ki < 8; ki++) {
                float4 hv = *reinterpret_cast<const float4*>(hp2 + ki * HROWS + c);
                ull h0 = pk2(hv.x, hv.x);
                ull h1 = pk2(hv.y, hv.y);
                ull h2 = pk2(hv.z, hv.z);
                ull h3 = pk2(hv.w, hv.w);
                acc[ki][0] = fma2_(h0, wa0.x, acc[ki][0]);
                acc[ki][1] = fma2_(h0, wa0.y, acc[ki][1]);
                acc[ki][2] = fma2_(h0, wa1.x, acc[ki][2]);
                acc[ki][3] = fma2_(h0, wa1.y, acc[ki][3]);
                acc[ki][0] = fma2_(h1, wb0.x, acc[ki][0]);
                acc[ki][1] = fma2_(h1, wb0.y, acc[ki][1]);
                acc[ki][2] = fma2_(h1, wb1.x, acc[ki][2]);
                acc[ki][3] = fma2_(h1, wb1.y, acc[ki][3]);
                acc[ki][0] = fma2_(h2, wc0.x, acc[ki][0]);
                acc[ki][1] = fma2_(h2, wc0.y, acc[ki][1]);
                acc[ki][2] = fma2_(h2, wc1.x, acc[ki][2]);
                acc[ki][3] = fma2_(h2, wc1.y, acc[ki][3]);
                acc[ki][0] = fma2_(h3, wd0.x, acc[ki][0]);
                acc[ki][1] = fma2_(h3, wd0.y, acc[ki][1]);
                acc[ki][2] = fma2_(h3, wd1.x, acc[ki][2]);
                acc[ki][3] = fma2_(h3, wd1.y, acc[ki][3]);
            }
        }
    }
    __syncthreads();
#pragma unroll
    for (int ki = 0; ki < 8; ki++) {
        float a0, a1, a2, a3, a4, a5, a6, a7;
        upk2(a0, a1, acc[ki][0]);
        upk2(a2, a3, acc[ki][1]);
        upk2(a4, a5, acc[ki][2]);
        upk2(a6, a7, acc[ki][3]);
        float4 v0 = make_float4(leaky(a0), leaky(a1), leaky(a2), leaky(a3));
        float4 v1 = make_float4(leaky(a4), leaky(a5), leaky(a6), leaky(a7));
        *reinterpret_cast<float4*>(hp2 + ki * HROWS + o0)     = v0;
        *reinterpret_cast<float4*>(hp2 + ki * HROWS + o0 + 4) = v1;
    }
    __syncthreads();

    // =============== layer 2 ===============
    {
        ulonglong2 bA = *reinterpret_cast<const ulonglong2*>(b1s + o0);
        ulonglong2 bB = *reinterpret_cast<const ulonglong2*>(b1s + o0 + 4);
#pragma unroll
        for (int ki = 0; ki < 8; ki++) {
            acc[ki][0] = bA.x; acc[ki][1] = bA.y;
            acc[ki][2] = bB.x; acc[ki][3] = bB.y;
        }
#pragma unroll 1
        for (int c = 0; c < 64; c += 4) {
            const float* wp = g_w1T + c * WSTR + o0;
            ulonglong2 wa0 = *reinterpret_cast<const ulonglong2*>(wp);
            ulonglong2 wa1 = *reinterpret_cast<const ulonglong2*>(wp + 4);
            ulonglong2 wb0 = *reinterpret_cast<const ulonglong2*>(wp + WSTR);
            ulonglong2 wb1 = *reinterpret_cast<const ulonglong2*>(wp + WSTR + 4);
            ulonglong2 wc0 = *reinterpret_cast<const ulonglong2*>(wp + 2 * WSTR);
            ulonglong2 wc1 = *reinterpret_cast<const ulonglong2*>(wp + 2 * WSTR + 4);
            ulonglong2 wd0 = *reinterpret_cast<const ulonglong2*>(wp + 3 * WSTR);
            ulonglong2 wd1 = *reinterpret_cast<const ulonglong2*>(wp + 3 * WSTR + 4);
#pragma unroll
            for (int ki = 0; ki < 8; ki++) {
                float4 hv = *reinterpret_cast<const float4*>(hp2 + ki * HROWS + c);
                ull h0 = pk2(hv.x, hv.x);
                ull h1 = pk2(hv.y, hv.y);
                ull h2 = pk2(hv.z, hv.z);
                ull h3 = pk2(hv.w, hv.w);
                acc[ki][0] = fma2_(h0, wa0.x, acc[ki][0]);
                acc[ki][1] = fma2_(h0, wa0.y, acc[ki][1]);
                acc[ki][2] = fma2_(h0, wa1.x, acc[ki][2]);
                acc[ki][3] = fma2_(h0, wa1.y, acc[ki][3]);
                acc[ki][0] = fma2_(h1, wb0.x, acc[ki][0]);
                acc[ki][1] = fma2_(h1, wb0.y, acc[ki][1]);
                acc[ki][2] = fma2_(h1, wb1.x, acc[ki][2]);
                acc[ki][3] = fma2_(h1, wb1.y, acc[ki][3]);
                acc[ki][0] = fma2_(h2, wc0.x, acc[ki][0]);
                acc[ki][1] = fma2_(h2, wc0.y, acc[ki][1]);
                acc[ki][2] = fma2_(h2, wc1.x, acc[ki][2]);
                acc[ki][3] = fma2_(h2, wc1.y, acc[ki][3]);
                acc[ki][0] = fma2_(h3, wd0.x, acc[ki][0]);
                acc[ki][1] = fma2_(h3, wd0.y, acc[ki][1]);
                acc[ki][2] = fma2_(h3, wd1.x, acc[ki][2]);
                acc[ki][3] = fma2_(h3, wd1.y, acc[ki][3]);
            }
        }
    }

    __syncthreads();   // hs dead; pm aliases it

    {
        float mx[8];
#pragma unroll
        for (int j = 0; j < 8; j++) mx[j] = -CUDART_INF_F;
#pragma unroll
        for (int ki = 0; ki < 8; ki++) {
            float a0, a1, a2, a3, a4, a5, a6, a7;
            upk2(a0, a1, acc[ki][0]);
            upk2(a2, a3, acc[ki][1]);
            upk2(a4, a5, acc[ki][2]);
            upk2(a6, a7, acc[ki][3]);
            mx[0] = fmaxf(mx[0], leaky(a0));
            mx[1] = fmaxf(mx[1], leaky(a1));
            mx[2] = fmaxf(mx[2], leaky(a2));
            mx[3] = fmaxf(mx[3], leaky(a3));
            mx[4] = fmaxf(mx[4], leaky(a4));
            mx[5] = fmaxf(mx[5], leaky(a5));
            mx[6] = fmaxf(mx[6], leaky(a6));
            mx[7] = fmaxf(mx[7], leaky(a7));
        }
        float* pmp = pm + p * 128 + (k0 >> 3) * 64 + o0;
        *reinterpret_cast<float4*>(pmp)     = make_float4(mx[0], mx[1], mx[2], mx[3]);
        *reinterpret_cast<float4*>(pmp + 4) = make_float4(mx[4], mx[5], mx[6], mx[7]);
    }
    __syncthreads();

#pragma unroll
    for (int i = 0; i < 4; i++) {
        int ii = tid + i * 128;
        int pp = ii >> 6, oo = ii & 63;
        float mm = fmaxf(pm[pp * 128 + oo], pm[pp * 128 + 64 + oo]);
        int nn = blockIdx.x * 8 + pp;
        g_ms[((size_t)dirb * NPTS + nn) * CH + oo] = mm;
    }
}

// ---------------------------------------------------------------------------
// proj (unchanged)
// ---------------------------------------------------------------------------
#define PPROJ 64
__global__ void __launch_bounds__(128) proj_kernel(
        const float* __restrict__ t1w, const float* __restrict__ t1b,
        const float* __restrict__ t2w, const float* __restrict__ t2b,
        float* __restrict__ out) {
    __shared__ float aS[PPROJ * 64];

    const int dir = blockIdx.z;
    const int b   = blockIdx.y;
    const int j   = threadIdx.x;
    const int dirb = dir * BATCH + b;

    const float* tw = dir ? t2w : t1w;
    const float* tb = dir ? t2b : t1b;

    float4 w[16];
#pragma unroll
    for (int t = 0; t < 16; t++)
        w[t] = reinterpret_cast<const float4*>(tw + j * 64)[t];
    const float bias = tb[j];

    const int n0 = blockIdx.x * PPROJ;
#pragma unroll
    for (int i = 0; i < PPROJ * 64 / 128 / 4; i++) {
        int f = j + i * 128;
        reinterpret_cast<float4*>(aS)[f] =
            reinterpret_cast<const float4*>(g_ms + ((size_t)dirb * NPTS + n0) * CH)[f];
    }
    __syncthreads();

#pragma unroll 2
    for (int p = 0; p < PPROJ; p++) {
        float acc = bias;
        const float4* ap = reinterpret_cast<const float4*>(aS + p * 64);
#pragma unroll
        for (int t = 0; t < 16; t++) {
            float4 a = ap[t];
            acc = fmaf(a.x, w[t].x, acc);
            acc = fmaf(a.y, w[t].y, acc);
            acc = fmaf(a.z, w[t].z, acc);
            acc = fmaf(a.w, w[t].w, acc);
        }
        out[((size_t)dirb * NPTS + n0 + p) * OUTCH + j] = acc;
    }
}

// ---------------------------------------------------------------------------
extern "C" void kernel_launch(void* const* d_in, const int* in_sizes, int n_in,
                              void* d_out, int out_size) {
    (void)in_sizes; (void)n_in; (void)out_size;
    const float* pc1   = (const float*)d_in[0];
    const float* pc2   = (const float*)d_in[1];
    const float* feat1 = (const float*)d_in[2];
    const float* feat2 = (const float*)d_in[3];
    const float* pos_w = (const float*)d_in[4];
    const float* pos_b = (const float*)d_in[5];
    const float* w0    = (const float*)d_in[6];
    const float* b0    = (const float*)d_in[7];
    const float* w1    = (const float*)d_in[8];
    const float* b1    = (const float*)d_in[9];
    const float* t1w   = (const float*)d_in[10];
    const float* t1b   = (const float*)d_in[11];
    const float* t2w   = (const float*)d_in[12];
    const float* t2b   = (const float*)d_in[13];
    float* out = (float*)d_out;

    pack_kernel<<<(2 * BATCH * NPTS + 255) / 256, 256>>>(pc1, pc2);
    wprep_kernel<<<4, 256>>>(w0, w1);

    // 64KB candidate tile + 8KB ushort slot-major idx = 72KB
    const size_t ksmem = 4 * SEGSZ * sizeof(float) + NSAMPLE * KBT * sizeof(ushort);
    cudaFuncSetAttribute(knn_kernel,
                         cudaFuncAttributeMaxDynamicSharedMemorySize, (int)ksmem);
    dim3 gk(NPTS / KBT, 2 * BATCH);
    knn_kernel<<<gk, KBT, ksmem>>>();

    const size_t smem = (size_t)(8 * HPNT + 192 + 64 * 3) * sizeof(float);
    cudaFuncSetAttribute(feat_kernel,
                         cudaFuncAttributeMaxDynamicSharedMemorySize, (int)smem);
    dim3 gf(NPTS / 8, BATCH, 2);
    feat_kernel<<<gf, 128, smem>>>(feat1, feat2, pos_w, pos_b, b0, b1);

    dim3 gp(NPTS / PPROJ, BATCH, 2);
    proj_kernel<<<gp, 128>>>(t1w, t1b, t2w, t2b, out);
}